// round 16
// baseline (speedup 1.0000x reference)
#include <cuda_runtime.h>
#include <cuda_fp16.h>
#include <cstdint>
#include <cstddef>

#define Bdim 8
#define Ndim 2048
#define Ddim 64
#define Hdim 128
#define DEG  16
#define Mrows (Bdim * Ndim)   // 16384

// ---------------- scratch (device globals; no allocations allowed) ----------
__device__ __half g_se_h[3][(size_t)Mrows * Hdim];   // 3 x 4 MB
__device__ __half g_ie_h[3][(size_t)Mrows * Hdim];   // 3 x 4 MB
__device__ __half g_aggr_h[(size_t)Mrows * Hdim];    // 4 MB
__device__ __half g_hu_h[(size_t)Mrows * Hdim];      // 4 MB

// Pre-packed fp16 weight fragments, exact mma.m16n8k16 B layout:
// [wsel][c16 (<=16)][nt (16)][lane (32)][2 x u32]
__device__ uint32_t g_BfH[6 * 16 * 16 * 32 * 2];     // 384 KB

// ---------------- helpers ---------------------------------------------------
__device__ __forceinline__ uint32_t smem_u32(const void* p) {
    uint32_t a;
    asm("{ .reg .u64 t; cvta.to.shared.u64 t, %1; cvt.u32.u64 %0, t; }"
        : "=r"(a) : "l"(p));
    return a;
}

__device__ __forceinline__ void split_pair_f16(float x, float y,
                                               uint32_t& hi, uint32_t& lo) {
    __half hx = __float2half_rn(x);
    __half hy = __float2half_rn(y);
    __half2 h2 = __halves2half2(hx, hy);
    hi = *reinterpret_cast<uint32_t*>(&h2);
    float rx = x - __half2float(hx);
    float ry = y - __half2float(hy);
    __half2 l2 = __halves2half2(__float2half_rn(rx), __float2half_rn(ry));
    lo = *reinterpret_cast<uint32_t*>(&l2);
}

__device__ __forceinline__ uint32_t pack_f16(float x, float y) {
    __half2 h = __halves2half2(__float2half_rn(x), __float2half_rn(y));
    return *reinterpret_cast<uint32_t*>(&h);
}

__device__ __forceinline__ void mma16816(float* d, const uint32_t* a,
                                         uint32_t b0, uint32_t b1) {
    asm volatile(
        "mma.sync.aligned.m16n8k16.row.col.f32.f16.f16.f32 "
        "{%0,%1,%2,%3}, {%4,%5,%6,%7}, {%8,%9}, {%0,%1,%2,%3};"
        : "+f"(d[0]), "+f"(d[1]), "+f"(d[2]), "+f"(d[3])
        : "r"(a[0]), "r"(a[1]), "r"(a[2]), "r"(a[3]), "r"(b0), "r"(b1));
}

__device__ __forceinline__ void ldsm_x4(uint32_t* r, uint32_t addr) {
    asm volatile("ldmatrix.sync.aligned.m8n8.x4.shared.b16 {%0,%1,%2,%3}, [%4];"
                 : "=r"(r[0]), "=r"(r[1]), "=r"(r[2]), "=r"(r[3]) : "r"(addr));
}

// ---------------- weight prep: W[k][128] -> fp16 B fragments ----------------
__global__ __launch_bounds__(512) void prep_weights(
    const float* W1, const float* W2, const float* W3,
    const float* Wu1, const float* Wu2, const float* Wu3)
{
    int bc = blockIdx.x;
    int wsel, c0;
    if      (bc < 4)  { wsel = 0; c0 = 0;  }
    else if (bc < 12) { wsel = 1; c0 = 4;  }
    else if (bc < 20) { wsel = 2; c0 = 12; }
    else if (bc < 36) { wsel = 3; c0 = 20; }
    else if (bc < 52) { wsel = 4; c0 = 36; }
    else              { wsel = 5; c0 = 52; }
    int c16 = bc - c0;
    const float* W = (wsel == 0) ? W1 : (wsel == 1) ? W2 : (wsel == 2) ? W3 :
                     (wsel == 3) ? Wu1 : (wsel == 4) ? Wu2 : Wu3;

    int t    = threadIdx.x;
    int nt   = t >> 5;
    int lane = t & 31;
    int g    = lane >> 2;
    int tig  = lane & 3;
    int n    = nt * 8 + g;
    int k0   = c16 * 16 + tig * 2;

    float w00 = W[(size_t)k0 * Hdim + n];
    float w01 = W[(size_t)(k0 + 1) * Hdim + n];
    float w10 = W[(size_t)(k0 + 8) * Hdim + n];
    float w11 = W[(size_t)(k0 + 9) * Hdim + n];

    size_t base = (((size_t)wsel * 256 + c16 * 16 + nt) * 32 + lane) * 2;
    g_BfH[base]     = pack_f16(w00, w01);
    g_BfH[base + 1] = pack_f16(w10, w11);
}

// ---------------- shared GEMM geometry --------------------------------------
constexpr int SA32_STRIDE = 80;
constexpr int SA32_TERM   = 64 * SA32_STRIDE;   // 5120 B
constexpr int SA32_BUF    = 2 * SA32_TERM;      // 10240 B per stage (hi+lo)

constexpr int SAH_STRIDE  = 144;                // 64 f16 = 128 B + 16 pad
constexpr int SAH_BUF     = 64 * SAH_STRIDE;    // 9216 B per stage

__device__ __forceinline__ void gemm_epilogue(
    float dacc[2][2][4], const float* bias,
    float* Cf, __half* Ch, int rb, int wm, int wn, int lid)
{
    const int g   = lid >> 2;
    const int tig = lid & 3;
#pragma unroll
    for (int mt = 0; mt < 2; mt++) {
        int row0 = rb + wm * 32 + mt * 16 + g;
#pragma unroll
        for (int nt = 0; nt < 2; nt++) {
            int col = (wn * 2 + nt) * 8 + tig * 2;
            float2 bb = *(const float2*)(bias + col);
            float2 o0, o1;
            o0.x = fmaxf(dacc[mt][nt][0] + bb.x, 0.f);
            o0.y = fmaxf(dacc[mt][nt][1] + bb.y, 0.f);
            o1.x = fmaxf(dacc[mt][nt][2] + bb.x, 0.f);
            o1.y = fmaxf(dacc[mt][nt][3] + bb.y, 0.f);
            if (Cf) {
                *(float2*)(Cf + (size_t)row0 * Hdim + col)       = o0;
                *(float2*)(Cf + (size_t)(row0 + 8) * Hdim + col) = o1;
            }
            if (Ch) {
                *(uint32_t*)(Ch + (size_t)row0 * Hdim + col)       = pack_f16(o0.x, o0.y);
                *(uint32_t*)(Ch + (size_t)(row0 + 8) * Hdim + col) = pack_f16(o1.x, o1.y);
            }
        }
    }
}

// ---------------- fp32-input core (2-term exact split, KC=32) ---------------
__device__ __forceinline__ void gemm_core_f32(
    char* sA, const float* __restrict__ A, int K,
    const uint32_t* __restrict__ BfH, const float* __restrict__ bias,
    __half* __restrict__ Ch, int rb)
{
    const int tid = threadIdx.x;
    const int wid = tid >> 5;
    const int lid = tid & 31;
    const int wm  = wid >> 3;
    const int wn  = wid & 7;
    const int NC  = K >> 5;

    const uint32_t sbase = smem_u32(sA);
    float dacc[2][2][4];
#pragma unroll
    for (int mt = 0; mt < 2; mt++)
#pragma unroll
        for (int nt = 0; nt < 2; nt++)
#pragma unroll
            for (int i = 0; i < 4; i++) dacc[mt][nt][i] = 0.f;

    const int r = tid >> 3;
    const int q = tid & 7;
    const uint32_t lrow = (uint32_t)(wm * 32 + (lid & 15)) * SA32_STRIDE
                        + (uint32_t)(lid >> 4) * 16;
    const uint32_t boff0 = (uint32_t)(((wn * 2) * 32 + lid) * 2);
    const uint32_t* bpH = BfH + boff0;

    float va[4];

#define LOADCHUNK32(c) do {                                                   \
        const float* ga = A + (size_t)(rb + r) * K + (c) * 32 + q * 4;        \
        *(float4*)&va[0] = *(const float4*)(ga);                              \
    } while (0)

#define CVTSTORE32(buf) do {                                                  \
        uint32_t hi[2], lo[2];                                                \
        split_pair_f16(va[0], va[1], hi[0], lo[0]);                           \
        split_pair_f16(va[2], va[3], hi[1], lo[1]);                           \
        char* dst = sA + (buf) * SA32_BUF + r * SA32_STRIDE + q * 8;          \
        *(uint2*)dst              = make_uint2(hi[0], hi[1]);                 \
        *(uint2*)(dst + SA32_TERM) = make_uint2(lo[0], lo[1]);                \
    } while (0)

    LOADCHUNK32(0);
    CVTSTORE32(0);
    __syncthreads();

    for (int c = 0; c < NC; c++) {
        const bool more = (c + 1 < NC);
        if (more) LOADCHUNK32(c + 1);
        const uint32_t bufbase = sbase + (c & 1) * SA32_BUF;
        const uint32_t cb = (uint32_t)(c * 2) * 1024u;
#pragma unroll
        for (int ks = 0; ks < 2; ks++) {
            uint32_t ah[2][4], al[2][4];
#pragma unroll
            for (int mt = 0; mt < 2; mt++) {
                uint32_t addr = bufbase + lrow
                              + (uint32_t)(mt * 16) * SA32_STRIDE
                              + (uint32_t)ks * 32;
                ldsm_x4(ah[mt], addr);
                ldsm_x4(al[mt], addr + SA32_TERM);
            }
            const uint32_t kb = cb + (uint32_t)ks * 1024u;
            uint2 bh[2];
#pragma unroll
            for (int nt = 0; nt < 2; nt++)
                bh[nt] = *(const uint2*)(bpH + kb + nt * 64);
#pragma unroll
            for (int nt = 0; nt < 2; nt++)
                mma16816(dacc[0][nt], ah[0], bh[nt].x, bh[nt].y);
#pragma unroll
            for (int nt = 0; nt < 2; nt++)
                mma16816(dacc[1][nt], ah[1], bh[nt].x, bh[nt].y);
#pragma unroll
            for (int nt = 0; nt < 2; nt++)
                mma16816(dacc[0][nt], al[0], bh[nt].x, bh[nt].y);
#pragma unroll
            for (int nt = 0; nt < 2; nt++)
                mma16816(dacc[1][nt], al[1], bh[nt].x, bh[nt].y);
        }
        if (more) CVTSTORE32((c + 1) & 1);
        __syncthreads();
    }
#undef LOADCHUNK32
#undef CVTSTORE32

    gemm_epilogue(dacc, bias, nullptr, Ch, rb, wm, wn, lid);
}

// ---------------- fp16-input core (single term, KC=64) ----------------------
__device__ __forceinline__ void gemm_core_h(
    char* sA,
    const __half* __restrict__ A1, int K1,
    const __half* __restrict__ A2, int K2,
    const uint32_t* __restrict__ BfH, const float* __restrict__ bias,
    float* __restrict__ Cf, __half* __restrict__ Ch, int rb)
{
    const int tid = threadIdx.x;
    const int wid = tid >> 5;
    const int lid = tid & 31;
    const int wm  = wid >> 3;
    const int wn  = wid & 7;
    const int NC  = (K1 + K2) >> 6;

    const uint32_t sbase = smem_u32(sA);
    float dacc[2][2][4];
#pragma unroll
    for (int mt = 0; mt < 2; mt++)
#pragma unroll
        for (int nt = 0; nt < 2; nt++)
#pragma unroll
            for (int i = 0; i < 4; i++) dacc[mt][nt][i] = 0.f;

    const int r = tid >> 3;
    const int q = tid & 7;
    const uint32_t lrow = (uint32_t)(wm * 32 + (lid & 15)) * SAH_STRIDE
                        + (uint32_t)(lid >> 4) * 16;
    const uint32_t boff0 = (uint32_t)(((wn * 2) * 32 + lid) * 2);
    const uint32_t* bpH = BfH + boff0;

    uint4 va;

#define LOADCHUNKH(c) do {                                                    \
        int g0 = (c) * 64; const __half* seg; int lda, koff;                  \
        if (g0 < K1) { seg = A1; lda = K1; koff = g0; }                       \
        else         { seg = A2; lda = K2; koff = g0 - K1; }                  \
        const __half* ga = seg + (size_t)(rb + r) * lda + koff + q * 8;       \
        va = *(const uint4*)ga;                                               \
    } while (0)

#define CVTSTOREH(buf) do {                                                   \
        char* dst = sA + (buf) * SAH_BUF + r * SAH_STRIDE + q * 16;           \
        *(uint4*)dst = va;                                                    \
    } while (0)

    LOADCHUNKH(0);
    CVTSTOREH(0);
    __syncthreads();

    for (int c = 0; c < NC; c++) {
        const bool more = (c + 1 < NC);
        if (more) LOADCHUNKH(c + 1);
        const uint32_t bufbase = sbase + (c & 1) * SAH_BUF;
        const uint32_t cb = (uint32_t)(c * 4) * 1024u;
#pragma unroll
        for (int ks = 0; ks < 4; ks++) {
            uint32_t ah[2][4];
#pragma unroll
            for (int mt = 0; mt < 2; mt++) {
                uint32_t addr = bufbase + lrow
                              + (uint32_t)(mt * 16) * SAH_STRIDE
                              + (uint32_t)ks * 32;
                ldsm_x4(ah[mt], addr);
            }
            const uint32_t kb = cb + (uint32_t)ks * 1024u;
            uint2 bh[2];
#pragma unroll
            for (int nt = 0; nt < 2; nt++)
                bh[nt] = *(const uint2*)(bpH + kb + nt * 64);
#pragma unroll
            for (int nt = 0; nt < 2; nt++)
                mma16816(dacc[0][nt], ah[0], bh[nt].x, bh[nt].y);
#pragma unroll
            for (int nt = 0; nt < 2; nt++)
                mma16816(dacc[1][nt], ah[1], bh[nt].x, bh[nt].y);
        }
        if (more) CVTSTOREH((c + 1) & 1);
        __syncthreads();
    }
#undef LOADCHUNKH
#undef CVTSTOREH

    gemm_epilogue(dacc, bias, Cf, Ch, rb, wm, wn, lid);
}

// ---------------- GEMM kernels ----------------------------------------------
__global__ __launch_bounds__(512) void gemm_dual_f32(
    const float* __restrict__ Aa, __half* __restrict__ Ca,
    const float* __restrict__ Ab, __half* __restrict__ Cb,
    int K, const uint32_t* __restrict__ BfH, const float* __restrict__ bias)
{
    __shared__ __align__(16) char sA[2 * SA32_BUF];
    const int nb = gridDim.x >> 1;
    if (blockIdx.x < nb)
        gemm_core_f32(sA, Aa, K, BfH, bias, Ca, blockIdx.x * 64);
    else
        gemm_core_f32(sA, Ab, K, BfH, bias, Cb, (blockIdx.x - nb) * 64);
}

// single fp16 GEMM (se or ie path); grid = 256
__global__ __launch_bounds__(512) void gemm_h_single(
    const __half* __restrict__ A, __half* __restrict__ C,
    const uint32_t* __restrict__ BfH, const float* __restrict__ bias)
{
    __shared__ __align__(16) char sA[2 * SAH_BUF];
    gemm_core_h(sA, A, Hdim, nullptr, 0, BfH, bias, nullptr, C,
                blockIdx.x * 64);
}

// concat GEMM: fp16 inputs, fp32 out (+ optional fp16 copy); grid = 256
__global__ __launch_bounds__(512) void gemm_cat_h(
    const __half* __restrict__ A1, const __half* __restrict__ A2,
    const uint32_t* __restrict__ BfH, const float* __restrict__ bias,
    float* __restrict__ Cf, __half* __restrict__ Ch)
{
    __shared__ __align__(16) char sA[2 * SAH_BUF];
    gemm_core_h(sA, A1, Hdim, A2, Hdim, BfH, bias, Cf, Ch, blockIdx.x * 64);
}

// ---------------- aggregation: fp16 in/out, smem gather-sum -----------------
constexpr int HC = 8;
constexpr int NSPLIT = 2;

__device__ __forceinline__ void acc_row_h(const char* base, float4& a0, float4& a1)
{
    uint4 v = *(const uint4*)base;
    float2 f0 = __half22float2(*reinterpret_cast<const __half2*>(&v.x));
    float2 f1 = __half22float2(*reinterpret_cast<const __half2*>(&v.y));
    float2 f2 = __half22float2(*reinterpret_cast<const __half2*>(&v.z));
    float2 f3 = __half22float2(*reinterpret_cast<const __half2*>(&v.w));
    a0.x += f0.x; a0.y += f0.y; a0.z += f1.x; a0.w += f1.y;
    a1.x += f2.x; a1.y += f2.y; a1.z += f3.x; a1.w += f3.y;
}

__global__ __launch_bounds__(256) void aggregate_kernel(
    const __half* __restrict__ se, const __half* __restrict__ ie,
    const int* __restrict__ sneigh, const int* __restrict__ ineigh,
    __half* __restrict__ aggr)
{
    extern __shared__ char smh[];
    char* sS = smh;
    char* sI = smh + Ndim * 16;
    const int b  = blockIdx.y;
    const int h0 = blockIdx.x * HC;
    const int nh = blockIdx.z;
    const int tid = threadIdx.x;

    const __half* seb = se + ((size_t)b * Ndim) * Hdim + h0;
    const __half* ieb = ie + ((size_t)b * Ndim) * Hdim + h0;
    for (int n = tid; n < Ndim; n += 256) {
        *(uint4*)(sS + n * 16) = *(const uint4*)(seb + (size_t)n * Hdim);
        *(uint4*)(sI + n * 16) = *(const uint4*)(ieb + (size_t)n * Hdim);
    }
    __syncthreads();

    const int n0 = nh * (Ndim / NSPLIT);
    const int n1 = n0 + (Ndim / NSPLIT);
    for (int n = n0 + tid; n < n1; n += 256) {
        float4 a0 = make_float4(0.f, 0.f, 0.f, 0.f);
        float4 a1 = make_float4(0.f, 0.f, 0.f, 0.f);
        const int4* is4 = (const int4*)(sneigh + n * DEG);
        const int4* ii4 = (const int4*)(ineigh + n * DEG);
#pragma unroll
        for (int qq = 0; qq < 4; qq++) {
            int4 v = is4[qq];
            acc_row_h(sS + v.x * 16, a0, a1);
            acc_row_h(sS + v.y * 16, a0, a1);
            acc_row_h(sS + v.z * 16, a0, a1);
            acc_row_h(sS + v.w * 16, a0, a1);
        }
#pragma unroll
        for (int qq = 0; qq < 4; qq++) {
            int4 v = ii4[qq];
            acc_row_h(sI + v.x * 16, a0, a1);
            acc_row_h(sI + v.y * 16, a0, a1);
            acc_row_h(sI + v.z * 16, a0, a1);
            acc_row_h(sI + v.w * 16, a0, a1);
        }
        __half* dst = aggr + ((size_t)b * Ndim + n) * Hdim + h0;
        uint4 pk;
        pk.x = pack_f16(a0.x, a0.y); pk.y = pack_f16(a0.z, a0.w);
        pk.z = pack_f16(a1.x, a1.y); pk.w = pack_f16(a1.z, a1.w);
        *(uint4*)dst = pk;
    }
}

// ---------------- launch ----------------------------------------------------
extern "C" void kernel_launch(void* const* d_in, const int* in_sizes, int n_in,
                              void* d_out, int out_size)
{
    const float* state     = (const float*)d_in[0];
    const float* internal_ = (const float*)d_in[1];
    const int*   sneigh    = (const int*)d_in[2];
    const int*   ineigh    = (const int*)d_in[3];
    const float* W1  = (const float*)d_in[4];
    const float* b1  = (const float*)d_in[5];
    const float* W2  = (const float*)d_in[6];
    const float* b2  = (const float*)d_in[7];
    const float* W3  = (const float*)d_in[8];
    const float* b3  = (const float*)d_in[9];
    const float* Wu1 = (const float*)d_in[10];
    const float* bu1 = (const float*)d_in[11];
    const float* Wu2 = (const float*)d_in[12];
    const float* bu2 = (const float*)d_in[13];
    const float* Wu3 = (const float*)d_in[14];
    const float* bu3 = (const float*)d_in[15];

    float* out = (float*)d_out;
    float* hu1 = out;
    float* hu2 = out + (size_t)Mrows * Hdim;
    float* hu3 = out + 2 * (size_t)Mrows * Hdim;

    void* p;
    cudaGetSymbolAddress(&p, g_se_h);   __half* seh = (__half*)p;
    cudaGetSymbolAddress(&p, g_ie_h);   __half* ieh = (__half*)p;
    cudaGetSymbolAddress(&p, g_aggr_h); __half* agg = (__half*)p;
    cudaGetSymbolAddress(&p, g_hu_h);   __half* huh = (__half*)p;
    cudaGetSymbolAddress(&p, g_BfH);    uint32_t* bfh = (uint32_t*)p;
    __half* se0 = seh;
    __half* se1 = seh + (size_t)Mrows * Hdim;
    __half* se2 = seh + 2 * (size_t)Mrows * Hdim;
    __half* ie0 = ieh;
    __half* ie1 = ieh + (size_t)Mrows * Hdim;
    __half* ie2 = ieh + 2 * (size_t)Mrows * Hdim;

    const uint32_t* BH[6];
    for (int i = 0; i < 6; i++)
        BH[i] = bfh + (size_t)i * 16384;

    // lazily-created side stream + events (created on first, non-capture call)
    static cudaStream_t s2 = nullptr;
    static cudaEvent_t eF1 = nullptr, eJ1 = nullptr, eJ2 = nullptr;
    if (!s2) {
        cudaStreamCreateWithFlags(&s2, cudaStreamNonBlocking);
        cudaEventCreateWithFlags(&eF1, cudaEventDisableTiming);
        cudaEventCreateWithFlags(&eJ1, cudaEventDisableTiming);
        cudaEventCreateWithFlags(&eJ2, cudaEventDisableTiming);
    }

    const int aggr_smem = Ndim * 16 * 2;     // 64 KB
    cudaFuncSetAttribute(aggregate_kernel,
                         cudaFuncAttributeMaxDynamicSharedMemorySize, aggr_smem);

    dim3 blkG(512);
    dim3 blkA(256);
    dim3 gDual(2 * (Mrows / 64));            // 512
    dim3 gSingle(Mrows / 64);                // 256
    dim3 gAgg(Hdim / HC, Bdim, NSPLIT);      // (16, 8, 2)

    prep_weights<<<68, 512>>>(W1, W2, W3, Wu1, Wu2, Wu3);

    // ---- Layer 1 encoder (both paths need fp32 inputs) ----
    gemm_dual_f32<<<gDual, blkG>>>(state, se0, internal_, ie0, Ddim, BH[0], b1);

    // fork: se-chain for layers 2-3 runs on side stream (depends only on se0)
    cudaEventRecord(eF1, 0);
    cudaStreamWaitEvent(s2, eF1, 0);
    gemm_h_single<<<gSingle, blkG, 0, s2>>>(se0, se1, BH[1], b2);  // seg2
    cudaEventRecord(eJ1, s2);
    gemm_h_single<<<gSingle, blkG, 0, s2>>>(se1, se2, BH[2], b3);  // seg3
    cudaEventRecord(eJ2, s2);

    // ---- main chain on default stream ----
    aggregate_kernel<<<gAgg, blkA, aggr_smem>>>(se0, ie0, sneigh, ineigh, agg);
    gemm_cat_h<<<gSingle, blkG>>>(agg, ie0, BH[3], bu1, hu1, huh);
    gemm_h_single<<<gSingle, blkG>>>(huh, ie1, BH[1], b2);         // ieg2

    cudaStreamWaitEvent(0, eJ1, 0);
    aggregate_kernel<<<gAgg, blkA, aggr_smem>>>(se1, ie1, sneigh, ineigh, agg);
    gemm_cat_h<<<gSingle, blkG>>>(agg, ie1, BH[4], bu2, hu2, huh);
    gemm_h_single<<<gSingle, blkG>>>(huh, ie2, BH[2], b3);         // ieg3

    cudaStreamWaitEvent(0, eJ2, 0);
    aggregate_kernel<<<gAgg, blkA, aggr_smem>>>(se2, ie2, sneigh, ineigh, agg);
    gemm_cat_h<<<gSingle, blkG>>>(agg, ie2, BH[5], bu3, hu3, nullptr);
}

// round 17
// speedup vs baseline: 1.1018x; 1.1018x over previous
#include <cuda_runtime.h>
#include <cuda_fp16.h>
#include <cstdint>
#include <cstddef>

#define Bdim 8
#define Ndim 2048
#define Ddim 64
#define Hdim 128
#define DEG  16
#define Mrows (Bdim * Ndim)   // 16384

// ---------------- scratch (device globals; no allocations allowed) ----------
__device__ __half g_se_h[3][(size_t)Mrows * Hdim];   // 3 x 4 MB
__device__ __half g_ie_h[3][(size_t)Mrows * Hdim];   // 3 x 4 MB
__device__ __half g_aggr_h[(size_t)Mrows * Hdim];    // 4 MB

// Pre-packed fp16 weight fragments, exact mma.m16n8k16 B layout:
// [wsel][c16 (<=16)][nt (16)][lane (32)][2 x u32]
__device__ uint32_t g_BfH[6 * 16 * 16 * 32 * 2];     // 384 KB

// ---------------- helpers ---------------------------------------------------
__device__ __forceinline__ uint32_t smem_u32(const void* p) {
    uint32_t a;
    asm("{ .reg .u64 t; cvta.to.shared.u64 t, %1; cvt.u32.u64 %0, t; }"
        : "=r"(a) : "l"(p));
    return a;
}

__device__ __forceinline__ void split_pair_f16(float x, float y,
                                               uint32_t& hi, uint32_t& lo) {
    __half hx = __float2half_rn(x);
    __half hy = __float2half_rn(y);
    __half2 h2 = __halves2half2(hx, hy);
    hi = *reinterpret_cast<uint32_t*>(&h2);
    float rx = x - __half2float(hx);
    float ry = y - __half2float(hy);
    __half2 l2 = __halves2half2(__float2half_rn(rx), __float2half_rn(ry));
    lo = *reinterpret_cast<uint32_t*>(&l2);
}

__device__ __forceinline__ uint32_t pack_f16(float x, float y) {
    __half2 h = __halves2half2(__float2half_rn(x), __float2half_rn(y));
    return *reinterpret_cast<uint32_t*>(&h);
}

__device__ __forceinline__ void mma16816(float* d, const uint32_t* a,
                                         uint32_t b0, uint32_t b1) {
    asm volatile(
        "mma.sync.aligned.m16n8k16.row.col.f32.f16.f16.f32 "
        "{%0,%1,%2,%3}, {%4,%5,%6,%7}, {%8,%9}, {%0,%1,%2,%3};"
        : "+f"(d[0]), "+f"(d[1]), "+f"(d[2]), "+f"(d[3])
        : "r"(a[0]), "r"(a[1]), "r"(a[2]), "r"(a[3]), "r"(b0), "r"(b1));
}

__device__ __forceinline__ void ldsm_x4(uint32_t* r, uint32_t addr) {
    asm volatile("ldmatrix.sync.aligned.m8n8.x4.shared.b16 {%0,%1,%2,%3}, [%4];"
                 : "=r"(r[0]), "=r"(r[1]), "=r"(r[2]), "=r"(r[3]) : "r"(addr));
}

// ---------------- weight prep: W[k][128] -> fp16 B fragments ----------------
__global__ __launch_bounds__(512) void prep_weights(
    const float* W1, const float* W2, const float* W3,
    const float* Wu1, const float* Wu2, const float* Wu3)
{
    int bc = blockIdx.x;
    int wsel, c0;
    if      (bc < 4)  { wsel = 0; c0 = 0;  }
    else if (bc < 12) { wsel = 1; c0 = 4;  }
    else if (bc < 20) { wsel = 2; c0 = 12; }
    else if (bc < 36) { wsel = 3; c0 = 20; }
    else if (bc < 52) { wsel = 4; c0 = 36; }
    else              { wsel = 5; c0 = 52; }
    int c16 = bc - c0;
    const float* W = (wsel == 0) ? W1 : (wsel == 1) ? W2 : (wsel == 2) ? W3 :
                     (wsel == 3) ? Wu1 : (wsel == 4) ? Wu2 : Wu3;

    int t    = threadIdx.x;
    int nt   = t >> 5;
    int lane = t & 31;
    int g    = lane >> 2;
    int tig  = lane & 3;
    int n    = nt * 8 + g;
    int k0   = c16 * 16 + tig * 2;

    float w00 = W[(size_t)k0 * Hdim + n];
    float w01 = W[(size_t)(k0 + 1) * Hdim + n];
    float w10 = W[(size_t)(k0 + 8) * Hdim + n];
    float w11 = W[(size_t)(k0 + 9) * Hdim + n];

    size_t base = (((size_t)wsel * 256 + c16 * 16 + nt) * 32 + lane) * 2;
    g_BfH[base]     = pack_f16(w00, w01);
    g_BfH[base + 1] = pack_f16(w10, w11);
}

// ---------------- shared GEMM geometry --------------------------------------
constexpr int SA32_STRIDE = 80;
constexpr int SA32_TERM   = 64 * SA32_STRIDE;   // 5120 B
constexpr int SA32_BUF    = 2 * SA32_TERM;      // 10240 B per stage (hi+lo)

constexpr int SAH_STRIDE  = 144;                // 64 f16 = 128 B + 16 pad
constexpr int SAH_BUF     = 64 * SAH_STRIDE;    // 9216 B per stage
constexpr int HU_STRIDE   = 272;                // 128 f16 = 256 B + 16 pad
// hu tile: 64 * 272 = 17408 B, aliases the two SAH stage buffers (18432 B)

__device__ __forceinline__ void gemm_epilogue(
    float dacc[2][2][4], const float* bias,
    float* Cf, __half* Ch, int rb, int wm, int wn, int lid)
{
    const int g   = lid >> 2;
    const int tig = lid & 3;
#pragma unroll
    for (int mt = 0; mt < 2; mt++) {
        int row0 = rb + wm * 32 + mt * 16 + g;
#pragma unroll
        for (int nt = 0; nt < 2; nt++) {
            int col = (wn * 2 + nt) * 8 + tig * 2;
            float2 bb = *(const float2*)(bias + col);
            float2 o0, o1;
            o0.x = fmaxf(dacc[mt][nt][0] + bb.x, 0.f);
            o0.y = fmaxf(dacc[mt][nt][1] + bb.y, 0.f);
            o1.x = fmaxf(dacc[mt][nt][2] + bb.x, 0.f);
            o1.y = fmaxf(dacc[mt][nt][3] + bb.y, 0.f);
            if (Cf) {
                *(float2*)(Cf + (size_t)row0 * Hdim + col)       = o0;
                *(float2*)(Cf + (size_t)(row0 + 8) * Hdim + col) = o1;
            }
            if (Ch) {
                *(uint32_t*)(Ch + (size_t)row0 * Hdim + col)       = pack_f16(o0.x, o0.y);
                *(uint32_t*)(Ch + (size_t)(row0 + 8) * Hdim + col) = pack_f16(o1.x, o1.y);
            }
        }
    }
}

// ---------------- fp32-input core (2-term exact split, KC=32) ---------------
__device__ __forceinline__ void gemm_core_f32(
    char* sA, const float* __restrict__ A, int K,
    const uint32_t* __restrict__ BfH, const float* __restrict__ bias,
    __half* __restrict__ Ch, int rb)
{
    const int tid = threadIdx.x;
    const int wid = tid >> 5;
    const int lid = tid & 31;
    const int wm  = wid >> 3;
    const int wn  = wid & 7;
    const int NC  = K >> 5;

    const uint32_t sbase = smem_u32(sA);
    float dacc[2][2][4];
#pragma unroll
    for (int mt = 0; mt < 2; mt++)
#pragma unroll
        for (int nt = 0; nt < 2; nt++)
#pragma unroll
            for (int i = 0; i < 4; i++) dacc[mt][nt][i] = 0.f;

    const int r = tid >> 3;
    const int q = tid & 7;
    const uint32_t lrow = (uint32_t)(wm * 32 + (lid & 15)) * SA32_STRIDE
                        + (uint32_t)(lid >> 4) * 16;
    const uint32_t boff0 = (uint32_t)(((wn * 2) * 32 + lid) * 2);
    const uint32_t* bpH = BfH + boff0;

    float va[4];

#define LOADCHUNK32(c) do {                                                   \
        const float* ga = A + (size_t)(rb + r) * K + (c) * 32 + q * 4;        \
        *(float4*)&va[0] = *(const float4*)(ga);                              \
    } while (0)

#define CVTSTORE32(buf) do {                                                  \
        uint32_t hi[2], lo[2];                                                \
        split_pair_f16(va[0], va[1], hi[0], lo[0]);                           \
        split_pair_f16(va[2], va[3], hi[1], lo[1]);                           \
        char* dst = sA + (buf) * SA32_BUF + r * SA32_STRIDE + q * 8;          \
        *(uint2*)dst              = make_uint2(hi[0], hi[1]);                 \
        *(uint2*)(dst + SA32_TERM) = make_uint2(lo[0], lo[1]);                \
    } while (0)

    LOADCHUNK32(0);
    CVTSTORE32(0);
    __syncthreads();

    for (int c = 0; c < NC; c++) {
        const bool more = (c + 1 < NC);
        if (more) LOADCHUNK32(c + 1);
        const uint32_t bufbase = sbase + (c & 1) * SA32_BUF;
        const uint32_t cb = (uint32_t)(c * 2) * 1024u;
#pragma unroll
        for (int ks = 0; ks < 2; ks++) {
            uint32_t ah[2][4], al[2][4];
#pragma unroll
            for (int mt = 0; mt < 2; mt++) {
                uint32_t addr = bufbase + lrow
                              + (uint32_t)(mt * 16) * SA32_STRIDE
                              + (uint32_t)ks * 32;
                ldsm_x4(ah[mt], addr);
                ldsm_x4(al[mt], addr + SA32_TERM);
            }
            const uint32_t kb = cb + (uint32_t)ks * 1024u;
            uint2 bh[2];
#pragma unroll
            for (int nt = 0; nt < 2; nt++)
                bh[nt] = *(const uint2*)(bpH + kb + nt * 64);
#pragma unroll
            for (int nt = 0; nt < 2; nt++)
                mma16816(dacc[0][nt], ah[0], bh[nt].x, bh[nt].y);
#pragma unroll
            for (int nt = 0; nt < 2; nt++)
                mma16816(dacc[1][nt], ah[1], bh[nt].x, bh[nt].y);
#pragma unroll
            for (int nt = 0; nt < 2; nt++)
                mma16816(dacc[0][nt], al[0], bh[nt].x, bh[nt].y);
#pragma unroll
            for (int nt = 0; nt < 2; nt++)
                mma16816(dacc[1][nt], al[1], bh[nt].x, bh[nt].y);
        }
        if (more) CVTSTORE32((c + 1) & 1);
        __syncthreads();
    }
#undef LOADCHUNK32
#undef CVTSTORE32

    gemm_epilogue(dacc, bias, nullptr, Ch, rb, wm, wn, lid);
}

// ---------------- fp16-input core (single term, KC=64) ----------------------
// Runs the K-loop into dacc; caller does the epilogue.
__device__ __forceinline__ void gemm_core_h_loop(
    char* sA, float dacc[2][2][4],
    const __half* __restrict__ A1, int K1,
    const __half* __restrict__ A2, int K2,
    const uint32_t* __restrict__ bpH,
    uint32_t lrow, int r, int q, int rb)
{
    const uint32_t sbase = smem_u32(sA);
    const int NC = (K1 + K2) >> 6;

    uint4 va;

#define LOADCHUNKH(c) do {                                                    \
        int g0 = (c) * 64; const __half* seg; int lda, koff;                  \
        if (g0 < K1) { seg = A1; lda = K1; koff = g0; }                       \
        else         { seg = A2; lda = K2; koff = g0 - K1; }                  \
        const __half* ga = seg + (size_t)(rb + r) * lda + koff + q * 8;       \
        va = *(const uint4*)ga;                                               \
    } while (0)

#define CVTSTOREH(buf) do {                                                   \
        char* dst = sA + (buf) * SAH_BUF + r * SAH_STRIDE + q * 16;           \
        *(uint4*)dst = va;                                                    \
    } while (0)

    LOADCHUNKH(0);
    CVTSTOREH(0);
    __syncthreads();

    for (int c = 0; c < NC; c++) {
        const bool more = (c + 1 < NC);
        if (more) LOADCHUNKH(c + 1);
        const uint32_t bufbase = sbase + (c & 1) * SAH_BUF;
        const uint32_t cb = (uint32_t)(c * 4) * 1024u;
#pragma unroll
        for (int ks = 0; ks < 4; ks++) {
            uint32_t ah[2][4];
#pragma unroll
            for (int mt = 0; mt < 2; mt++) {
                uint32_t addr = bufbase + lrow
                              + (uint32_t)(mt * 16) * SAH_STRIDE
                              + (uint32_t)ks * 32;
                ldsm_x4(ah[mt], addr);
            }
            const uint32_t kb = cb + (uint32_t)ks * 1024u;
            uint2 bh[2];
#pragma unroll
            for (int nt = 0; nt < 2; nt++)
                bh[nt] = *(const uint2*)(bpH + kb + nt * 64);
#pragma unroll
            for (int nt = 0; nt < 2; nt++)
                mma16816(dacc[0][nt], ah[0], bh[nt].x, bh[nt].y);
#pragma unroll
            for (int nt = 0; nt < 2; nt++)
                mma16816(dacc[1][nt], ah[1], bh[nt].x, bh[nt].y);
        }
        if (more) CVTSTOREH((c + 1) & 1);
        __syncthreads();
    }
#undef LOADCHUNKH
#undef CVTSTOREH
}

// ---------------- GEMM kernels ----------------------------------------------
// layer-1 dual: fp32 inputs (exact 2-term), fp16 outputs; grid = 512
__global__ __launch_bounds__(512) void gemm_dual_f32(
    const float* __restrict__ Aa, __half* __restrict__ Ca,
    const float* __restrict__ Ab, __half* __restrict__ Cb,
    int K, const uint32_t* __restrict__ BfH, const float* __restrict__ bias)
{
    __shared__ __align__(16) char sA[2 * SA32_BUF];
    const int nb = gridDim.x >> 1;
    if (blockIdx.x < nb)
        gemm_core_f32(sA, Aa, K, BfH, bias, Ca, blockIdx.x * 64);
    else
        gemm_core_f32(sA, Ab, K, BfH, bias, Cb, (blockIdx.x - nb) * 64);
}

// single fp16 GEMM (se path); grid = 256
__global__ __launch_bounds__(512) void gemm_h_single(
    const __half* __restrict__ A, __half* __restrict__ C,
    const uint32_t* __restrict__ BfH, const float* __restrict__ bias)
{
    __shared__ __align__(16) char sA[2 * SAH_BUF];
    const int tid = threadIdx.x;
    const int wid = tid >> 5;
    const int lid = tid & 31;
    const int wm  = wid >> 3;
    const int wn  = wid & 7;
    const int rb  = blockIdx.x * 64;
    const int r = tid >> 3, q = tid & 7;
    const uint32_t lrow = (uint32_t)(wm * 32 + (lid & 15)) * SAH_STRIDE
                        + (uint32_t)(lid >> 4) * 16;
    const uint32_t boff0 = (uint32_t)(((wn * 2) * 32 + lid) * 2);

    float dacc[2][2][4];
#pragma unroll
    for (int mt = 0; mt < 2; mt++)
#pragma unroll
        for (int nt = 0; nt < 2; nt++)
#pragma unroll
            for (int i = 0; i < 4; i++) dacc[mt][nt][i] = 0.f;

    gemm_core_h_loop(sA, dacc, A, Hdim, nullptr, 0, BfH + boff0,
                     lrow, r, q, rb);
    gemm_epilogue(dacc, bias, nullptr, C, rb, wm, wn, lid);
}

// plain concat GEMM (layer 3): fp16 inputs, fp32 out; grid = 256
__global__ __launch_bounds__(512) void gemm_cat_h(
    const __half* __restrict__ A1, const __half* __restrict__ A2,
    const uint32_t* __restrict__ BfH, const float* __restrict__ bias,
    float* __restrict__ Cf)
{
    __shared__ __align__(16) char sA[2 * SAH_BUF];
    const int tid = threadIdx.x;
    const int wid = tid >> 5;
    const int lid = tid & 31;
    const int wm  = wid >> 3;
    const int wn  = wid & 7;
    const int rb  = blockIdx.x * 64;
    const int r = tid >> 3, q = tid & 7;
    const uint32_t lrow = (uint32_t)(wm * 32 + (lid & 15)) * SAH_STRIDE
                        + (uint32_t)(lid >> 4) * 16;
    const uint32_t boff0 = (uint32_t)(((wn * 2) * 32 + lid) * 2);

    float dacc[2][2][4];
#pragma unroll
    for (int mt = 0; mt < 2; mt++)
#pragma unroll
        for (int nt = 0; nt < 2; nt++)
#pragma unroll
            for (int i = 0; i < 4; i++) dacc[mt][nt][i] = 0.f;

    gemm_core_h_loop(sA, dacc, A1, Hdim, A2, Hdim, BfH + boff0,
                     lrow, r, q, rb);
    gemm_epilogue(dacc, bias, Cf, nullptr, rb, wm, wn, lid);
}

// fused cat + next-layer ie GEMM: stage1 = relu(cat@Wu+bu) -> hu (fp32 global
// + fp16 smem tile); stage2 = relu(hu @ Wnext + bnext) -> ie_next (fp16).
// Row-local fusion: each block's hu tile feeds only its own stage-2 rows.
__global__ __launch_bounds__(512) void gemm_cat_fused(
    const __half* __restrict__ A1, const __half* __restrict__ A2,
    const uint32_t* __restrict__ Bf1, const float* __restrict__ bias1,
    float* __restrict__ Cf,
    const uint32_t* __restrict__ Bf2, const float* __restrict__ bias2,
    __half* __restrict__ C2)
{
    __shared__ __align__(16) char sA[2 * SAH_BUF];   // 18432 B; hu tile aliases
    const int tid = threadIdx.x;
    const int wid = tid >> 5;
    const int lid = tid & 31;
    const int wm  = wid >> 3;
    const int wn  = wid & 7;
    const int rb  = blockIdx.x * 64;
    const int r = tid >> 3, q = tid & 7;
    const uint32_t lrow = (uint32_t)(wm * 32 + (lid & 15)) * SAH_STRIDE
                        + (uint32_t)(lid >> 4) * 16;
    const uint32_t boff0 = (uint32_t)(((wn * 2) * 32 + lid) * 2);
    const uint32_t sbase = smem_u32(sA);

    float dacc[2][2][4];
#pragma unroll
    for (int mt = 0; mt < 2; mt++)
#pragma unroll
        for (int nt = 0; nt < 2; nt++)
#pragma unroll
            for (int i = 0; i < 4; i++) dacc[mt][nt][i] = 0.f;

    gemm_core_h_loop(sA, dacc, A1, Hdim, A2, Hdim, Bf1 + boff0,
                     lrow, r, q, rb);

    // --- stage-1 epilogue: fp32 hu to global + fp16 hu tile to smem ---------
    {
        const int g   = lid >> 2;
        const int tig = lid & 3;
#pragma unroll
        for (int mt = 0; mt < 2; mt++) {
            int lr0  = wm * 32 + mt * 16 + g;
            int row0 = rb + lr0;
#pragma unroll
            for (int nt = 0; nt < 2; nt++) {
                int col = (wn * 2 + nt) * 8 + tig * 2;
                float2 bb = *(const float2*)(bias1 + col);
                float2 o0, o1;
                o0.x = fmaxf(dacc[mt][nt][0] + bb.x, 0.f);
                o0.y = fmaxf(dacc[mt][nt][1] + bb.y, 0.f);
                o1.x = fmaxf(dacc[mt][nt][2] + bb.x, 0.f);
                o1.y = fmaxf(dacc[mt][nt][3] + bb.y, 0.f);
                *(float2*)(Cf + (size_t)row0 * Hdim + col)       = o0;
                *(float2*)(Cf + (size_t)(row0 + 8) * Hdim + col) = o1;
                *(uint32_t*)(sA + lr0 * HU_STRIDE + col * 2)       = pack_f16(o0.x, o0.y);
                *(uint32_t*)(sA + (lr0 + 8) * HU_STRIDE + col * 2) = pack_f16(o1.x, o1.y);
            }
        }
    }
    __syncthreads();

    // --- stage 2: ie_next = relu(hu_tile @ Wnext + bnext) --------------------
    float d2[2][2][4];
#pragma unroll
    for (int mt = 0; mt < 2; mt++)
#pragma unroll
        for (int nt = 0; nt < 2; nt++)
#pragma unroll
            for (int i = 0; i < 4; i++) d2[mt][nt][i] = 0.f;

    const uint32_t lrow2 = (uint32_t)(wm * 32 + (lid & 15)) * HU_STRIDE
                         + (uint32_t)(lid >> 4) * 16;
    const uint32_t* bp2 = Bf2 + boff0;
#pragma unroll
    for (int ks = 0; ks < 8; ks++) {
        uint32_t ah[2][4];
#pragma unroll
        for (int mt = 0; mt < 2; mt++) {
            uint32_t addr = sbase + lrow2
                          + (uint32_t)(mt * 16) * HU_STRIDE
                          + (uint32_t)ks * 32;
            ldsm_x4(ah[mt], addr);
        }
        const uint32_t kb = (uint32_t)ks * 1024u;
        uint2 bh[2];
#pragma unroll
        for (int nt = 0; nt < 2; nt++)
            bh[nt] = *(const uint2*)(bp2 + kb + nt * 64);
#pragma unroll
        for (int nt = 0; nt < 2; nt++)
            mma16816(d2[0][nt], ah[0], bh[nt].x, bh[nt].y);
#pragma unroll
        for (int nt = 0; nt < 2; nt++)
            mma16816(d2[1][nt], ah[1], bh[nt].x, bh[nt].y);
    }
    gemm_epilogue(d2, bias2, nullptr, C2, rb, wm, wn, lid);
}

// ---------------- aggregation: fp16 in/out, smem gather-sum -----------------
constexpr int HC = 8;
constexpr int NSPLIT = 2;

__device__ __forceinline__ void acc_row_h(const char* base, float4& a0, float4& a1)
{
    uint4 v = *(const uint4*)base;
    float2 f0 = __half22float2(*reinterpret_cast<const __half2*>(&v.x));
    float2 f1 = __half22float2(*reinterpret_cast<const __half2*>(&v.y));
    float2 f2 = __half22float2(*reinterpret_cast<const __half2*>(&v.z));
    float2 f3 = __half22float2(*reinterpret_cast<const __half2*>(&v.w));
    a0.x += f0.x; a0.y += f0.y; a0.z += f1.x; a0.w += f1.y;
    a1.x += f2.x; a1.y += f2.y; a1.z += f3.x; a1.w += f3.y;
}

__global__ __launch_bounds__(256) void aggregate_kernel(
    const __half* __restrict__ se, const __half* __restrict__ ie,
    const int* __restrict__ sneigh, const int* __restrict__ ineigh,
    __half* __restrict__ aggr)
{
    extern __shared__ char smh[];
    char* sS = smh;
    char* sI = smh + Ndim * 16;
    const int b  = blockIdx.y;
    const int h0 = blockIdx.x * HC;
    const int nh = blockIdx.z;
    const int tid = threadIdx.x;

    const __half* seb = se + ((size_t)b * Ndim) * Hdim + h0;
    const __half* ieb = ie + ((size_t)b * Ndim) * Hdim + h0;
    for (int n = tid; n < Ndim; n += 256) {
        *(uint4*)(sS + n * 16) = *(const uint4*)(seb + (size_t)n * Hdim);
        *(uint4*)(sI + n * 16) = *(const uint4*)(ieb + (size_t)n * Hdim);
    }
    __syncthreads();

    const int n0 = nh * (Ndim / NSPLIT);
    const int n1 = n0 + (Ndim / NSPLIT);
    for (int n = n0 + tid; n < n1; n += 256) {
        float4 a0 = make_float4(0.f, 0.f, 0.f, 0.f);
        float4 a1 = make_float4(0.f, 0.f, 0.f, 0.f);
        const int4* is4 = (const int4*)(sneigh + n * DEG);
        const int4* ii4 = (const int4*)(ineigh + n * DEG);
#pragma unroll
        for (int qq = 0; qq < 4; qq++) {
            int4 v = is4[qq];
            acc_row_h(sS + v.x * 16, a0, a1);
            acc_row_h(sS + v.y * 16, a0, a1);
            acc_row_h(sS + v.z * 16, a0, a1);
            acc_row_h(sS + v.w * 16, a0, a1);
        }
#pragma unroll
        for (int qq = 0; qq < 4; qq++) {
            int4 v = ii4[qq];
            acc_row_h(sI + v.x * 16, a0, a1);
            acc_row_h(sI + v.y * 16, a0, a1);
            acc_row_h(sI + v.z * 16, a0, a1);
            acc_row_h(sI + v.w * 16, a0, a1);
        }
        __half* dst = aggr + ((size_t)b * Ndim + n) * Hdim + h0;
        uint4 pk;
        pk.x = pack_f16(a0.x, a0.y); pk.y = pack_f16(a0.z, a0.w);
        pk.z = pack_f16(a1.x, a1.y); pk.w = pack_f16(a1.z, a1.w);
        *(uint4*)dst = pk;
    }
}

// ---------------- launch ----------------------------------------------------
extern "C" void kernel_launch(void* const* d_in, const int* in_sizes, int n_in,
                              void* d_out, int out_size)
{
    const float* state     = (const float*)d_in[0];
    const float* internal_ = (const float*)d_in[1];
    const int*   sneigh    = (const int*)d_in[2];
    const int*   ineigh    = (const int*)d_in[3];
    const float* W1  = (const float*)d_in[4];
    const float* b1  = (const float*)d_in[5];
    const float* W2  = (const float*)d_in[6];
    const float* b2  = (const float*)d_in[7];
    const float* W3  = (const float*)d_in[8];
    const float* b3  = (const float*)d_in[9];
    const float* Wu1 = (const float*)d_in[10];
    const float* bu1 = (const float*)d_in[11];
    const float* Wu2 = (const float*)d_in[12];
    const float* bu2 = (const float*)d_in[13];
    const float* Wu3 = (const float*)d_in[14];
    const float* bu3 = (const float*)d_in[15];

    float* out = (float*)d_out;
    float* hu1 = out;
    float* hu2 = out + (size_t)Mrows * Hdim;
    float* hu3 = out + 2 * (size_t)Mrows * Hdim;

    void* p;
    cudaGetSymbolAddress(&p, g_se_h);   __half* seh = (__half*)p;
    cudaGetSymbolAddress(&p, g_ie_h);   __half* ieh = (__half*)p;
    cudaGetSymbolAddress(&p, g_aggr_h); __half* agg = (__half*)p;
    cudaGetSymbolAddress(&p, g_BfH);    uint32_t* bfh = (uint32_t*)p;
    __half* se0 = seh;
    __half* se1 = seh + (size_t)Mrows * Hdim;
    __half* se2 = seh + 2 * (size_t)Mrows * Hdim;
    __half* ie0 = ieh;
    __half* ie1 = ieh + (size_t)Mrows * Hdim;
    __half* ie2 = ieh + 2 * (size_t)Mrows * Hdim;

    const uint32_t* BH[6];
    for (int i = 0; i < 6; i++)
        BH[i] = bfh + (size_t)i * 16384;

    const int aggr_smem = Ndim * 16 * 2;     // 64 KB
    cudaFuncSetAttribute(aggregate_kernel,
                         cudaFuncAttributeMaxDynamicSharedMemorySize, aggr_smem);

    dim3 blkG(512);
    dim3 blkA(256);
    dim3 gDual(2 * (Mrows / 64));            // 512
    dim3 gSingle(Mrows / 64);                // 256
    dim3 gAgg(Hdim / HC, Bdim, NSPLIT);      // (16, 8, 2)

    prep_weights<<<68, 512>>>(W1, W2, W3, Wu1, Wu2, Wu3);

    // ---- Layer 1 ----
    gemm_dual_f32<<<gDual, blkG>>>(state, se0, internal_, ie0, Ddim, BH[0], b1);
    aggregate_kernel<<<gAgg, blkA, aggr_smem>>>(se0, ie0, sneigh, ineigh, agg);
    // cat1 fused with ie-GEMM of layer 2 (row-local)
    gemm_cat_fused<<<gSingle, blkG>>>(agg, ie0, BH[3], bu1, hu1,
                                      BH[1], b2, ie1);

    // ---- Layer 2 ----
    gemm_h_single<<<gSingle, blkG>>>(se0, se1, BH[1], b2);   // se-GEMM L2
    aggregate_kernel<<<gAgg, blkA, aggr_smem>>>(se1, ie1, sneigh, ineigh, agg);
    gemm_cat_fused<<<gSingle, blkG>>>(agg, ie1, BH[4], bu2, hu2,
                                      BH[2], b3, ie2);

    // ---- Layer 3 ----
    gemm_h_single<<<gSingle, blkG>>>(se1, se2, BH[2], b3);   // se-GEMM L3
    aggregate_kernel<<<gAgg, blkA, aggr_smem>>>(se2, ie2, sneigh, ineigh, agg);
    gemm_cat_h<<<gSingle, blkG>>>(agg, ie2, BH[5], bu3, hu3);
}